// round 14
// baseline (speedup 1.0000x reference)
#include <cuda_runtime.h>
#include <cuda_fp16.h>
#include <cstdint>

// x[32768,2048] fp32, bank[20,2048] fp32 -> out[32768,2048] fp32
constexpr int FEA    = 2048;
constexpr int NBANK  = 20;
constexpr int TILE_M = 64;             // 512 tiles
constexpr int CHUNK  = 128;            // x cols per chunk
constexpr int NCH    = FEA / CHUNK;    // 16
constexpr int NTH    = 512;            // 16 warps
constexpr float LAMBDA = 0.0025f;

// SMEM map (176128 B -> 1 CTA/SM)
constexpr int SM_BANK  = 0;                        // [32 j pad][2048 k] fp16 swz
constexpr int BANKB    = 32 * FEA * 2;             // 131072
constexpr int SM_X     = BANKB;                    // x fp16 ring: 2 x 16KB
constexpr int XSLOTB   = TILE_M * CHUNK * 2;       // 16384
constexpr int SM_LOGIT = SM_X + 2 * XSLOTB;        // 163840: [64][32] f32
constexpr int SM_ATT   = SM_LOGIT + 64 * 32 * 4;   // 172032: [64][32] fp16
constexpr int SM_TOTAL = SM_ATT + 64 * 32 * 2;     // 176128

__device__ unsigned int g_tilectr;
__global__ void reset_ctr() { g_tilectr = 0u; }

__device__ __forceinline__ uint32_t s2u(const void* p) {
    uint32_t a;
    asm("{ .reg .u64 t; cvta.to.shared.u64 t, %1; cvt.u32.u64 %0, t; }"
        : "=r"(a) : "l"(p));
    return a;
}
__device__ __forceinline__ void ldsm4(uint32_t a, uint32_t& r0, uint32_t& r1,
                                      uint32_t& r2, uint32_t& r3) {
    asm volatile("ldmatrix.sync.aligned.m8n8.x4.shared.b16 {%0,%1,%2,%3}, [%4];"
                 : "=r"(r0), "=r"(r1), "=r"(r2), "=r"(r3) : "r"(a));
}
__device__ __forceinline__ void ldsm4t(uint32_t a, uint32_t& r0, uint32_t& r1,
                                       uint32_t& r2, uint32_t& r3) {
    asm volatile("ldmatrix.sync.aligned.m8n8.x4.trans.shared.b16 {%0,%1,%2,%3}, [%4];"
                 : "=r"(r0), "=r"(r1), "=r"(r2), "=r"(r3) : "r"(a));
}
__device__ __forceinline__ void mma16816(float& d0, float& d1, float& d2, float& d3,
                                         uint32_t a0, uint32_t a1, uint32_t a2, uint32_t a3,
                                         uint32_t b0, uint32_t b1) {
    asm volatile(
        "mma.sync.aligned.m16n8k16.row.col.f32.f16.f16.f32 "
        "{%0,%1,%2,%3}, {%4,%5,%6,%7}, {%8,%9}, {%0,%1,%2,%3};"
        : "+f"(d0), "+f"(d1), "+f"(d2), "+f"(d3)
        : "r"(a0), "r"(a1), "r"(a2), "r"(a3), "r"(b0), "r"(b1));
}
__device__ __forceinline__ float tanh_fast(float v) {
    float r;
    asm("tanh.approx.f32 %0, %1;" : "=f"(r) : "f"(v));
    return r;
}
__device__ __forceinline__ uint32_t h2bits(__half2 h) {
    return *reinterpret_cast<uint32_t*>(&h);
}

extern __shared__ char smc[];

__global__ void __launch_bounds__(NTH, 1)
memunit_q64(const float* __restrict__ x,
            const float* __restrict__ bank,
            float* __restrict__ out,
            int n_tiles)
{
    __shared__ int s_next;
    const uint32_t sbase = s2u(smc);
    const int tid  = threadIdx.x;
    const int warp = tid >> 5;
    const int lane = tid & 31;

    // ---- bank -> fp16 [32 j pad][2048], swizzle byte = j*4096 + (2k ^ ((j&7)<<4))
    for (int i = tid; i < BANKB / 16; i += NTH)
        reinterpret_cast<uint4*>(smc + SM_BANK)[i] = make_uint4(0, 0, 0, 0);
    __syncthreads();
    for (int idx = tid; idx < NBANK * FEA; idx += NTH) {
        const int j = idx >> 11, k = idx & (FEA - 1);
        *reinterpret_cast<__half*>(smc + SM_BANK + j * 4096 + ((2 * k) ^ ((j & 7) << 4)))
            = __float2half(bank[idx]);
    }

    // Decomposition (both GEMMs): mh = warp>>2 (m16 block 0..3), nt = warp&3
    const int mh = warp >> 2;
    const int nt = warp & 3;

    // A frags (row-major x4) from xh (256B rows)
    const int arow = mh * 16 + (lane & 7) + ((lane & 8) ? 8 : 0);
    const int akb  = (lane & 16) ? 16 : 0;
    const int asw  = (arow & 7) << 4;
    // GEMM1 B paired (x4 = 2 consecutive k16 steps): rows j = nt*8 + (lane&7)
    const int brow = nt * 8 + (lane & 7);
    const int bkb2 = ((lane & 8) ? 16 : 0) + ((lane & 16) ? 32 : 0);
    const int bsw  = (brow & 7) << 4;
    const uint32_t bb = sbase + SM_BANK + brow * 4096;
    // GEMM2 B (trans x4): j = lane (rows 20-31 zero pad)
    const uint32_t btl = sbase + SM_BANK + lane * 4096;
    const int swj = (lane & 7) << 4;
    // logit / out row mapping
    const int lr  = mh * 16 + (lane >> 2);
    const int lc2 = (lane & 3) * 2;
    // att frag row component
    const int frow = (lane & 7) + ((lane & 8) ? 8 : 0);
    const int fkb  = (lane & 16) ? 16 : 0;

    float4 pf[4];   // x prefetch: 16 f32/thread (one 64x128 chunk / 512 thr)

    auto ldx = [&](int tile, int c) {
        const float4* p = reinterpret_cast<const float4*>(x)
                        + (long)tile * TILE_M * (FEA / 4) + c * (CHUNK / 4);
        #pragma unroll
        for (int i = 0; i < 4; i++) {
            const int f = i * NTH + tid;              // float4 idx in chunk
            pf[i] = p[(f >> 5) * (FEA / 4) + (f & 31)];
        }
    };
    auto stx = [&](int slot) {
        char* s = smc + SM_X + slot * XSLOTB;
        #pragma unroll
        for (int i = 0; i < 4; i++) {
            const int f = i * NTH + tid;
            const int row = f >> 5, kb = (f & 31) * 8;
            uint2 pkt;
            pkt.x = h2bits(__floats2half2_rn(pf[i].x, pf[i].y));
            pkt.y = h2bits(__floats2half2_rn(pf[i].z, pf[i].w));
            *reinterpret_cast<uint2*>(s + row * 256 + (kb ^ ((row & 7) << 4))) = pkt;
        }
    };

    // ---- initial tile pop ------------------------------------------------
    if (tid == 0) s_next = (int)atomicAdd(&g_tilectr, 1u);
    __syncthreads();                                  // bank + s_next visible
    int cur = s_next;
    if (cur < n_tiles) ldx(cur, 0);

    bool haveA = false;       // att frags valid for tile at rowPrev
    long rowPrev = 0;
    uint32_t aA0[4], aA1[4];  // att frags (this warp's mh block)

    while (cur < n_tiles || haveA) {
        const bool g1 = cur < n_tiles;
        int nxt = n_tiles;                            // latched at c == 1
        float d0 = 0.f, d1 = 0.f, d2 = 0.f, d3 = 0.f;
        float* o0 = out + (rowPrev + mh * 16 + (lane >> 2)) * FEA + lc2;

        #pragma unroll 1
        for (int c = 0; c < NCH; c++) {
            if (g1) {
                stx(c & 1);
                if (c == 0 && tid == 0) s_next = (int)atomicAdd(&g_tilectr, 1u);
                if (c + 1 < NCH)           ldx(cur, c + 1);
                else if (nxt < n_tiles)    ldx(nxt, 0);
            }
            __syncthreads();      // xh[c&1] ready (double-buffer: one bar)
            if (g1 && c == 1) nxt = s_next;   // pop (pre-bar c=0) -> read post-bar

            if (g1) {
                const uint32_t xs = sbase + SM_X + (c & 1) * XSLOTB + arow * 256;
                const int cb = c * 256;       // bank row-byte base of chunk
                #pragma unroll
                for (int k2 = 0; k2 < 4; k2++) {
                    uint32_t a0, a1, a2, a3, a4, a5, a6, a7, b0, b1, b2, b3;
                    ldsm4(xs + ((k2 * 64 + akb) ^ asw),      a0, a1, a2, a3);
                    ldsm4(xs + ((k2 * 64 + 32 + akb) ^ asw), a4, a5, a6, a7);
                    ldsm4(bb + ((cb + k2 * 64 + bkb2) ^ bsw), b0, b1, b2, b3);
                    mma16816(d0, d1, d2, d3, a0, a1, a2, a3, b0, b1);
                    mma16816(d0, d1, d2, d3, a4, a5, a6, a7, b2, b3);
                }
            }

            if (haveA) {
                // GEMM2 + tanh: this warp's 4 n8-blocks of the 128-col chunk
                #pragma unroll
                for (int i = 0; i < 4; i++) {
                    const int nb = c * 128 + nt * 32 + i * 8;
                    uint32_t b00, b01, b10, b11;
                    ldsm4t(btl + ((nb * 2) ^ swj), b00, b01, b10, b11);
                    float e0 = 0.f, e1 = 0.f, e2 = 0.f, e3 = 0.f;
                    mma16816(e0, e1, e2, e3, aA0[0], aA0[1], aA0[2], aA0[3], b00, b01);
                    mma16816(e0, e1, e2, e3, aA1[0], aA1[1], aA1[2], aA1[3], b10, b11);
                    *reinterpret_cast<float2*>(o0 + nb) =
                        make_float2(tanh_fast(e0), tanh_fast(e1));
                    *reinterpret_cast<float2*>(o0 + 8 * FEA + nb) =
                        make_float2(tanh_fast(e2), tanh_fast(e3));
                }
            }
        }

        if (g1) {
            // ---- logits -> SMEM ------------------------------------------
            float* lg = reinterpret_cast<float*>(smc + SM_LOGIT);
            *reinterpret_cast<float2*>(&lg[lr * 32 + nt * 8 + lc2])       = make_float2(d0, d1);
            *reinterpret_cast<float2*>(&lg[(lr + 8) * 32 + nt * 8 + lc2]) = make_float2(d2, d3);
            __syncthreads();

            // ---- softmax -> softshrink -> softmax (1 thr/row, 64 rows) ---
            if (tid < 64) {
                float att[NBANK];
                #pragma unroll
                for (int j = 0; j < NBANK; j++) att[j] = lg[tid * 32 + j];

                float m = att[0];
                #pragma unroll
                for (int j = 1; j < NBANK; j++) m = fmaxf(m, att[j]);
                float s = 0.f;
                #pragma unroll
                for (int j = 0; j < NBANK; j++) { float e = __expf(att[j] - m); att[j] = e; s += e; }
                const float inv = 1.0f / s;

                float m2 = 0.f;   // att >= 0 => softshrink = max(att - lambda, 0)
                #pragma unroll
                for (int j = 0; j < NBANK; j++) {
                    float a = fmaxf(att[j] * inv - LAMBDA, 0.f);
                    att[j] = a;
                    m2 = fmaxf(m2, a);
                }
                float s2 = 0.f;
                #pragma unroll
                for (int j = 0; j < NBANK; j++) { float e = __expf(att[j] - m2); att[j] = e; s2 += e; }
                const float inv2 = 1.0f / s2;

                __half2* av = reinterpret_cast<__half2*>(smc + SM_ATT + tid * 64);
                #pragma unroll
                for (int jp = 0; jp < 10; jp++)
                    av[jp] = __floats2half2_rn(att[2 * jp] * inv2, att[2 * jp + 1] * inv2);
                #pragma unroll
                for (int jp = 10; jp < 16; jp++)
                    av[jp] = __floats2half2_rn(0.f, 0.f);
            }
            __syncthreads();

            // ---- preload att frags (this warp's mh block) ----------------
            const uint32_t ab = sbase + SM_ATT + (mh * 16 + frow) * 64 + fkb;
            ldsm4(ab,      aA0[0], aA0[1], aA0[2], aA0[3]);   // k = j 0..15
            ldsm4(ab + 32, aA1[0], aA1[1], aA1[2], aA1[3]);   // k = j 16..31

            haveA = true;
            rowPrev = (long)cur * TILE_M;
        } else {
            haveA = false;
        }
        cur = nxt;
    }
}

extern "C" void kernel_launch(void* const* d_in, const int* in_sizes, int n_in,
                              void* d_out, int out_size)
{
    const float* x    = reinterpret_cast<const float*>(d_in[0]);
    const float* bank = reinterpret_cast<const float*>(d_in[1]);
    float* out        = reinterpret_cast<float*>(d_out);

    const int rows    = in_sizes[0] / FEA;   // 32768
    const int n_tiles = rows / TILE_M;       // 512

    cudaFuncSetAttribute(memunit_q64,
                         cudaFuncAttributeMaxDynamicSharedMemorySize, SM_TOTAL);

    int dev = 0, sms = 148;
    cudaGetDevice(&dev);
    cudaDeviceGetAttribute(&sms, cudaDevAttrMultiProcessorCount, dev);

    const int grid = (sms < n_tiles) ? sms : n_tiles;

    reset_ctr<<<1, 1>>>();
    memunit_q64<<<grid, NTH, SM_TOTAL>>>(x, bank, out, n_tiles);
}

// round 15
// speedup vs baseline: 1.2198x; 1.2198x over previous
#include <cuda_runtime.h>
#include <cuda_fp16.h>
#include <cstdint>

// x[32768,2048] fp32, bank[20,2048] fp32 -> out[32768,2048] fp32
constexpr int FEA    = 2048;
constexpr int NBANK  = 20;
constexpr int RU     = 16;            // rows per unit (one warp per unit)
constexpr int KC     = 32;            // k cols per chunk
constexpr int NCHK   = FEA / KC;      // 64
constexpr int DEPTH  = 4;             // per-warp cp.async ring slots
constexpr int NTH    = 512;           // 16 warps
constexpr float LAMBDA = 0.0025f;

// SMEM map (214016 B, 1 CTA/SM)
constexpr int SM_BANK = 0;                       // [20 j][2048 k] fp16 swz
constexpr int BANKB   = NBANK * 4096;            // 81920
constexpr int SM_ZP   = BANKB;                   // 1KB zero page
constexpr int SM_XR   = SM_ZP + 1024;            // 16 warps x 4 x 2KB fp32 slots
constexpr int SLOTB   = RU * KC * 4;             // 2048
constexpr int SM_TOTAL = SM_XR + 16 * DEPTH * SLOTB;   // 214016

__device__ __forceinline__ uint32_t s2u(const void* p) {
    uint32_t a;
    asm("{ .reg .u64 t; cvta.to.shared.u64 t, %1; cvt.u32.u64 %0, t; }"
        : "=r"(a) : "l"(p));
    return a;
}
__device__ __forceinline__ void ldsm4(uint32_t a, uint32_t& r0, uint32_t& r1,
                                      uint32_t& r2, uint32_t& r3) {
    asm volatile("ldmatrix.sync.aligned.m8n8.x4.shared.b16 {%0,%1,%2,%3}, [%4];"
                 : "=r"(r0), "=r"(r1), "=r"(r2), "=r"(r3) : "r"(a));
}
__device__ __forceinline__ void ldsm4t(uint32_t a, uint32_t& r0, uint32_t& r1,
                                       uint32_t& r2, uint32_t& r3) {
    asm volatile("ldmatrix.sync.aligned.m8n8.x4.trans.shared.b16 {%0,%1,%2,%3}, [%4];"
                 : "=r"(r0), "=r"(r1), "=r"(r2), "=r"(r3) : "r"(a));
}
__device__ __forceinline__ void mma16816(float& d0, float& d1, float& d2, float& d3,
                                         uint32_t a0, uint32_t a1, uint32_t a2, uint32_t a3,
                                         uint32_t b0, uint32_t b1) {
    asm volatile(
        "mma.sync.aligned.m16n8k16.row.col.f32.f16.f16.f32 "
        "{%0,%1,%2,%3}, {%4,%5,%6,%7}, {%8,%9}, {%0,%1,%2,%3};"
        : "+f"(d0), "+f"(d1), "+f"(d2), "+f"(d3)
        : "r"(a0), "r"(a1), "r"(a2), "r"(a3), "r"(b0), "r"(b1));
}
__device__ __forceinline__ float tanh_fast(float v) {
    float r;
    asm("tanh.approx.f32 %0, %1;" : "=f"(r) : "f"(v));
    return r;
}
__device__ __forceinline__ uint32_t h2(float lo, float hi) {
    __half2 h = __floats2half2_rn(lo, hi);
    return *reinterpret_cast<uint32_t*>(&h);
}
__device__ __forceinline__ void cp16(uint32_t dst, const float* src) {
    asm volatile("cp.async.cg.shared.global [%0], [%1], 16;" :: "r"(dst), "l"(src));
}
__device__ __forceinline__ float2 lds64(uint32_t a) {
    float2 v;
    asm volatile("ld.shared.v2.f32 {%0,%1}, [%2];" : "=f"(v.x), "=f"(v.y) : "r"(a));
    return v;
}
__device__ __forceinline__ float redmax4(float v) {
    v = fmaxf(v, __shfl_xor_sync(0xffffffffu, v, 1));
    v = fmaxf(v, __shfl_xor_sync(0xffffffffu, v, 2));
    return v;
}
__device__ __forceinline__ float redsum4(float v) {
    v += __shfl_xor_sync(0xffffffffu, v, 1);
    v += __shfl_xor_sync(0xffffffffu, v, 2);
    return v;
}

extern __shared__ char smc[];

__global__ void __launch_bounds__(NTH, 1)
memunit_wa(const float* __restrict__ x,
           const float* __restrict__ bank,
           float* __restrict__ out,
           int units)
{
    const uint32_t sbase = s2u(smc);
    const int tid  = threadIdx.x;
    const int warp = tid >> 5;
    const int lane = tid & 31;

    // ---- bank -> fp16 [20 j][2048 k], swizzle byte = j*4096 + (2k ^ ((j&7)<<4))
    for (int idx = tid; idx < NBANK * FEA; idx += NTH) {
        const int j = idx >> 11, k = idx & (FEA - 1);
        *reinterpret_cast<__half*>(smc + SM_BANK + j * 4096 + ((2 * k) ^ ((j & 7) << 4)))
            = __float2half(bank[idx]);
    }
    for (int i = tid; i < 1024 / 4; i += NTH)
        reinterpret_cast<uint32_t*>(smc + SM_ZP)[i] = 0u;
    __syncthreads();   // the ONLY CTA-wide barrier

    const int unit = (int)blockIdx.x + (int)gridDim.x * warp;
    if (unit >= units) return;

    const long row0 = (long)unit * RU;
    const int rA  = lane >> 2;            // 0..7 (rowB = rA + 8)
    const int m   = lane & 3;
    const bool v2 = m < 2;                // block2 (cols 16..19) validity
    const int swj = (lane & 7) << 4;
    const bool jv = lane < NBANK;
    const uint32_t btlv = sbase + SM_BANK + lane * 4096;        // j = lane
    const uint32_t zp   = sbase + SM_ZP + (lane & 15) * 16;
    const uint32_t ring = sbase + SM_XR + warp * (DEPTH * SLOTB);
    const int rsw = rA << 4;              // (row&7)<<4, same for rA and rA+8

    // issue one k32 chunk into its ring slot (always commit to keep counts)
    auto issue = [&](int c) {
        if (c < NCHK) {
            const uint32_t db = ring + (c & (DEPTH - 1)) * SLOTB;
            #pragma unroll
            for (int i = 0; i < 4; i++) {
                const int f = i * 32 + lane;          // 16B piece 0..127
                const int row = f >> 3, g = f & 7;
                cp16(db + row * 128 + ((g * 16) ^ ((row & 7) << 4)),
                     x + (row0 + row) * FEA + c * KC + g * 4);
            }
        }
        asm volatile("cp.async.commit_group;" ::: "memory");
    };

    // ================= GEMM1: d[b][0..3] over k = 0..2047 ===================
    float d[4][4];
    #pragma unroll
    for (int b = 0; b < 4; b++)
        #pragma unroll
        for (int q = 0; q < 4; q++) d[b][q] = 0.f;

    issue(0); issue(1); issue(2);

    #pragma unroll 2
    for (int c = 0; c < NCHK; c++) {
        asm volatile("cp.async.wait_group %0;" :: "n"(2) : "memory");
        __syncwarp();
        issue(c + 3);

        const uint32_t sb = ring + (c & (DEPTH - 1)) * SLOTB;
        #pragma unroll
        for (int ks = 0; ks < 2; ks++) {
            const int cb = ks * 64 + m * 8;
            const float2 f0 = lds64(sb + rA * 128 + (cb ^ rsw));
            const float2 f1 = lds64(sb + (rA + 8) * 128 + (cb ^ rsw));
            const float2 f2 = lds64(sb + rA * 128 + ((cb + 32) ^ rsw));
            const float2 f3 = lds64(sb + (rA + 8) * 128 + ((cb + 32) ^ rsw));
            const uint32_t a0 = h2(f0.x, f0.y);
            const uint32_t a1 = h2(f1.x, f1.y);
            const uint32_t a2 = h2(f2.x, f2.y);
            const uint32_t a3 = h2(f3.x, f3.y);

            const int colb = c * 64 + ks * 32;
            uint32_t B0[4], B1[4];
            ldsm4(jv ? btlv + (colb ^ swj) : zp,        B0[0], B0[1], B0[2], B0[3]);
            ldsm4(jv ? btlv + ((colb + 16) ^ swj) : zp, B1[0], B1[1], B1[2], B1[3]);
            #pragma unroll
            for (int b = 0; b < 4; b++)
                mma16816(d[b][0], d[b][1], d[b][2], d[b][3],
                         a0, a1, a2, a3, B0[b], B1[b]);
        }
    }

    // ============ in-warp softmax -> softshrink -> softmax ==================
    // rowA = rA: vals d[b][0] (col 8b+2m), d[b][1]; rowB = rA+8: d[b][2], d[b][3]
    // valid: b=0,1 all; b=2 iff m<2; b=3 never.
    float AA[6], AB[6];
    {
        float mA = fmaxf(fmaxf(d[0][0], d[0][1]), fmaxf(d[1][0], d[1][1]));
        float mB = fmaxf(fmaxf(d[0][2], d[0][3]), fmaxf(d[1][2], d[1][3]));
        if (v2) {
            mA = fmaxf(mA, fmaxf(d[2][0], d[2][1]));
            mB = fmaxf(mB, fmaxf(d[2][2], d[2][3]));
        }
        mA = redmax4(mA); mB = redmax4(mB);

        float eA[6], eB[6];
        #pragma unroll
        for (int b = 0; b < 2; b++) {
            eA[2*b]   = __expf(d[b][0] - mA); eA[2*b+1] = __expf(d[b][1] - mA);
            eB[2*b]   = __expf(d[b][2] - mB); eB[2*b+1] = __expf(d[b][3] - mB);
        }
        eA[4] = v2 ? __expf(d[2][0] - mA) : 0.f;
        eA[5] = v2 ? __expf(d[2][1] - mA) : 0.f;
        eB[4] = v2 ? __expf(d[2][2] - mB) : 0.f;
        eB[5] = v2 ? __expf(d[2][3] - mB) : 0.f;

        float sA = 0.f, sB = 0.f;
        #pragma unroll
        for (int i = 0; i < 6; i++) { sA += eA[i]; sB += eB[i]; }
        sA = redsum4(sA); sB = redsum4(sB);
        const float iA = 1.0f / sA, iB = 1.0f / sB;

        // softshrink (att >= 0): a = max(att - lambda, 0); invalid stay 0
        float m2A = 0.f, m2B = 0.f;
        #pragma unroll
        for (int i = 0; i < 6; i++) {
            AA[i] = fmaxf(eA[i] * iA - LAMBDA, 0.f);
            AB[i] = fmaxf(eB[i] * iB - LAMBDA, 0.f);
            m2A = fmaxf(m2A, AA[i]); m2B = fmaxf(m2B, AB[i]);
        }
        m2A = redmax4(m2A); m2B = redmax4(m2B);

        float s2A = 0.f, s2B = 0.f;
        #pragma unroll
        for (int i = 0; i < 6; i++) {
            const bool val = (i < 4) || v2;
            AA[i] = val ? __expf(AA[i] - m2A) : 0.f;
            AB[i] = val ? __expf(AB[i] - m2B) : 0.f;
            s2A += AA[i]; s2B += AB[i];
        }
        s2A = redsum4(s2A); s2B = redsum4(s2B);
        const float i2A = 1.0f / s2A, i2B = 1.0f / s2B;
        #pragma unroll
        for (int i = 0; i < 6; i++) { AA[i] *= i2A; AB[i] *= i2B; }
    }

    // pack att into GEMM2 A-frags (D-frag layout == A-frag layout)
    uint32_t aF0[4], aF1[4];
    aF0[0] = h2(AA[0], AA[1]); aF0[1] = h2(AB[0], AB[1]);   // k 0..15
    aF0[2] = h2(AA[2], AA[3]); aF0[3] = h2(AB[2], AB[3]);
    aF1[0] = h2(AA[4], AA[5]); aF1[1] = h2(AB[4], AB[5]);   // k 16..31 (j>=20 -> 0)
    aF1[2] = 0u;               aF1[3] = 0u;

    // ================= GEMM2 + tanh: out[16 x 2048] =========================
    float* o0 = out + (row0 + rA) * FEA + 2 * m;
    #pragma unroll 4
    for (int nb = 0; nb < 256; nb++) {
        const int colb = nb * 16;
        uint32_t b00, b01, b10, b11;
        ldsm4t(jv ? btlv + (colb ^ swj) : zp, b00, b01, b10, b11);
        float e0 = 0.f, e1 = 0.f, e2 = 0.f, e3 = 0.f;
        mma16816(e0, e1, e2, e3, aF0[0], aF0[1], aF0[2], aF0[3], b00, b01);
        mma16816(e0, e1, e2, e3, aF1[0], aF1[1], aF1[2], aF1[3], b10, b11);
        *reinterpret_cast<float2*>(o0 + nb * 8) =
            make_float2(tanh_fast(e0), tanh_fast(e1));
        *reinterpret_cast<float2*>(o0 + 8 * FEA + nb * 8) =
            make_float2(tanh_fast(e2), tanh_fast(e3));
    }
}

extern "C" void kernel_launch(void* const* d_in, const int* in_sizes, int n_in,
                              void* d_out, int out_size)
{
    const float* x    = reinterpret_cast<const float*>(d_in[0]);
    const float* bank = reinterpret_cast<const float*>(d_in[1]);
    float* out        = reinterpret_cast<float*>(d_out);

    const int rows  = in_sizes[0] / FEA;   // 32768
    const int units = rows / RU;           // 2048

    cudaFuncSetAttribute(memunit_wa,
                         cudaFuncAttributeMaxDynamicSharedMemorySize, SM_TOTAL);

    int dev = 0, sms = 148;
    cudaGetDevice(&dev);
    cudaDeviceGetAttribute(&sms, cudaDevAttrMultiProcessorCount, dev);

    const int grid = (sms < units) ? sms : units;
    memunit_wa<<<grid, NTH, SM_TOTAL>>>(x, bank, out, units);
}